// round 2
// baseline (speedup 1.0000x reference)
#include <cuda_runtime.h>
#include <cuda_bf16.h>
#include <cstdint>

#define NB 8192
#define NK 8192
#define ND 512
#define NM (8192ULL * 8192ULL)

// ---------------- static device scratch (no runtime allocation) ----------------
__device__ double g_A[NM];          // exp kernel matrix, fp64 (512 MB)
__device__ float  g_Dm[NM];         // d2 matrix, fp32 (256 MB)
__device__ float  g_nx[NB];
__device__ float  g_nc[NK];
__device__ double g_r[NB];
__device__ double g_c[NK];
__device__ double g_zpart[64 * NK]; // col-pass partials (deterministic reduce)
__device__ double g_Spart[2048];
__device__ double g_S;
__device__ unsigned g_maxbits;
__device__ unsigned g_minbits;
__device__ float  g_midf;
__device__ float  g_rangef;
__device__ int    g_idx[NB];

// monotonic float<->uint encoding for atomic max/min (order-independent -> deterministic)
__device__ __forceinline__ unsigned encf(float f) {
    unsigned u = __float_as_uint(f);
    return (u & 0x80000000u) ? ~u : (u | 0x80000000u);
}
__device__ __forceinline__ float decf(unsigned u) {
    return (u & 0x80000000u) ? __uint_as_float(u & 0x7FFFFFFFu) : __uint_as_float(~u);
}

// ---------------- reset (graph replay must fully re-init accumulators) ----------------
__global__ void reset_kernel() {
    if (blockIdx.x == 0 && threadIdx.x == 0) {
        g_maxbits = 0u;
        g_minbits = 0xFFFFFFFFu;
        g_S = 0.0;
    }
}

// ---------------- row norms: nx[i] = sum_d x[i,d]^2 (f64 acc -> f32) ----------------
__global__ __launch_bounds__(128) void norms_kernel(const float* __restrict__ X,
                                                    const float* __restrict__ C) {
    int row = blockIdx.x;
    const float* p = (blockIdx.y == 0 ? X : C) + (size_t)row * ND;
    float4 v = ((const float4*)p)[threadIdx.x];
    double s = (double)v.x * v.x + (double)v.y * v.y + (double)v.z * v.z + (double)v.w * v.w;
    for (int o = 16; o; o >>= 1) s += __shfl_down_sync(0xffffffffu, s, o);
    __shared__ double sm[4];
    if ((threadIdx.x & 31) == 0) sm[threadIdx.x >> 5] = s;
    __syncthreads();
    if (threadIdx.x == 0) {
        double t = (sm[0] + sm[1]) + (sm[2] + sm[3]);
        if (blockIdx.y == 0) g_nx[row] = (float)t; else g_nc[row] = (float)t;
    }
}

// ---------------- fp32 GEMM: d2[i][j] = nx[i]+nc[j]-2*sum_k X[i,k]C[j,k] ----------------
// 128x128 tile, 256 threads, 8x8 microtile, k-panel 16. Fused d2 + global min/max.
__global__ __launch_bounds__(256) void gemm_kernel(const float* __restrict__ X,
                                                   const float* __restrict__ C) {
    __shared__ float As[16][132];
    __shared__ float Bs[16][132];
    const int tid = threadIdx.x;
    const int bi = blockIdx.y << 7;
    const int bj = blockIdx.x << 7;
    const int tr = (tid >> 4) << 3;
    const int tc = (tid & 15) << 3;
    const int lrow = tid >> 2;
    const int lk = (tid & 3) << 2;
    float acc[8][8];
#pragma unroll
    for (int p = 0; p < 8; p++)
#pragma unroll
        for (int q = 0; q < 8; q++) acc[p][q] = 0.f;

    for (int k0 = 0; k0 < ND; k0 += 16) {
#pragma unroll
        for (int rep = 0; rep < 2; rep++) {
            int r = lrow + (rep << 6);
            float4 va = *(const float4*)(X + (size_t)(bi + r) * ND + k0 + lk);
            As[lk + 0][r] = va.x; As[lk + 1][r] = va.y; As[lk + 2][r] = va.z; As[lk + 3][r] = va.w;
            float4 vb = *(const float4*)(C + (size_t)(bj + r) * ND + k0 + lk);
            Bs[lk + 0][r] = vb.x; Bs[lk + 1][r] = vb.y; Bs[lk + 2][r] = vb.z; Bs[lk + 3][r] = vb.w;
        }
        __syncthreads();
#pragma unroll
        for (int kk = 0; kk < 16; kk++) {
            float a[8], b[8];
#pragma unroll
            for (int p = 0; p < 8; p++) a[p] = As[kk][tr + p];
#pragma unroll
            for (int q = 0; q < 8; q++) b[q] = Bs[kk][tc + q];
#pragma unroll
            for (int p = 0; p < 8; p++)
#pragma unroll
                for (int q = 0; q < 8; q++) acc[p][q] += a[p] * b[q];
        }
        __syncthreads();
    }

    // epilogue: d2 + local min/max
    float nxv[8], ncv[8];
#pragma unroll
    for (int p = 0; p < 8; p++) nxv[p] = g_nx[bi + tr + p];
#pragma unroll
    for (int q = 0; q < 8; q++) ncv[q] = g_nc[bj + tc + q];
    float lmx = -3.4e38f, lmn = 3.4e38f;
#pragma unroll
    for (int p = 0; p < 8; p++) {
        float d2v[8];
#pragma unroll
        for (int q = 0; q < 8; q++) {
            float d2 = (nxv[p] + ncv[q]) - 2.0f * acc[p][q];
            d2v[q] = d2;
            lmx = fmaxf(lmx, d2);
            lmn = fminf(lmn, d2);
        }
        float* dst = g_Dm + (size_t)(bi + tr + p) * NK + bj + tc;
        *(float4*)(dst)     = make_float4(d2v[0], d2v[1], d2v[2], d2v[3]);
        *(float4*)(dst + 4) = make_float4(d2v[4], d2v[5], d2v[6], d2v[7]);
    }
    for (int o = 16; o; o >>= 1) {
        lmx = fmaxf(lmx, __shfl_down_sync(0xffffffffu, lmx, o));
        lmn = fminf(lmn, __shfl_down_sync(0xffffffffu, lmn, o));
    }
    __shared__ float smx[8], smn[8];
    if ((tid & 31) == 0) { smx[tid >> 5] = lmx; smn[tid >> 5] = lmn; }
    __syncthreads();
    if (tid == 0) {
#pragma unroll
        for (int w = 1; w < 8; w++) { lmx = fmaxf(lmx, smx[w]); lmn = fminf(lmn, smn[w]); }
        atomicMax(&g_maxbits, encf(lmx));
        atomicMin(&g_minbits, encf(lmn));
    }
}

__global__ void finalize_kernel() {
    float mx = decf(g_maxbits), mn = decf(g_minbits);
    float mid = (mx + mn) * 0.5f;      // matches ref fp32 arithmetic
    g_midf = mid;
    g_rangef = (mx - mid) + 1e-8f;
}

// ---------------- fill A = exp(-d2n/eps), fp64 via fp32 exp2 + exponent splice ----------------
__device__ __forceinline__ double exp_splice(float u, float cfh, float cfl) {
    float zf = u * cfh;
    float nf = floorf(zf);
    float ff = fmaf(u, cfh, -nf) + u * cfl;     // high-precision fractional log2
    double m = (double)exp2f(ff);               // ~[1,2), slight spill ok
    long long n = (long long)nf;
    return __longlong_as_double(__double_as_longlong(m) + (n << 52)); // m * 2^n exactly
}

__global__ __launch_bounds__(256) void fill_kernel() {
    const float midf = g_midf;
    const float rangef = g_rangef;
    const double CFd = -480.89834696298781;     // -log2(e)/0.003
    const float cfh = (float)CFd;
    const float cfl = (float)(CFd - (double)cfh);
    double s = 0.0;
    size_t stride = (size_t)gridDim.x * blockDim.x;
    for (size_t i4 = (size_t)blockIdx.x * blockDim.x + threadIdx.x; i4 < NM / 4; i4 += stride) {
        float4 d2 = ((const float4*)g_Dm)[i4];
        double a0 = exp_splice((d2.x - midf) / rangef, cfh, cfl);
        double a1 = exp_splice((d2.y - midf) / rangef, cfh, cfl);
        double a2 = exp_splice((d2.z - midf) / rangef, cfh, cfl);
        double a3 = exp_splice((d2.w - midf) / rangef, cfh, cfl);
        double2* dst = (double2*)(g_A + i4 * 4);
        dst[0] = make_double2(a0, a1);
        dst[1] = make_double2(a2, a3);
        s += (a0 + a1) + (a2 + a3);
    }
    for (int o = 16; o; o >>= 1) s += __shfl_down_sync(0xffffffffu, s, o);
    __shared__ double sm[8];
    if ((threadIdx.x & 31) == 0) sm[threadIdx.x >> 5] = s;
    __syncthreads();
    if (threadIdx.x == 0) {
        double t = 0.0;
#pragma unroll
        for (int w = 0; w < 8; w++) t += sm[w];
        g_Spart[blockIdx.x] = t;   // fixed slot -> deterministic
    }
}

__global__ __launch_bounds__(1024) void reduceS_kernel() {
    int tid = threadIdx.x;
    double s = g_Spart[tid] + g_Spart[tid + 1024];
    __shared__ double sm[1024];
    sm[tid] = s;
    __syncthreads();
    for (int o = 512; o; o >>= 1) {
        if (tid < o) sm[tid] += sm[tid + o];
        __syncthreads();
    }
    if (tid == 0) g_S = sm[0];
}

__global__ void init_rc_kernel() {
    int t = blockIdx.x * blockDim.x + threadIdx.x;
    double S = g_S;
    if (t < NB) g_r[t] = 1.0 / S;
    if (t < NK) g_c[t] = 1.0;
}

// ---------------- Sinkhorn row pass: y_i = sum_j A[i][j] c[j]; update r ----------------
__global__ __launch_bounds__(256) void row_pass_kernel() {
    int i = blockIdx.x;
    const double* Arow = g_A + (size_t)i * NK;
    double s = 0.0;
#pragma unroll 4
    for (int j = threadIdx.x * 2; j < NK; j += 512) {
        double2 a = *(const double2*)(Arow + j);
        double2 cc = *(const double2*)(g_c + j);
        s += a.x * cc.x + a.y * cc.y;
    }
    for (int o = 16; o; o >>= 1) s += __shfl_down_sync(0xffffffffu, s, o);
    __shared__ double sm[8];
    if ((threadIdx.x & 31) == 0) sm[threadIdx.x >> 5] = s;
    __syncthreads();
    if (threadIdx.x == 0) {
        double y = 0.0;
#pragma unroll
        for (int w = 0; w < 8; w++) y += sm[w];
        double r = g_r[i];
        g_r[i] = r / ((r * y) + 1e-8) / (double)NB;
    }
}

// ---------------- Sinkhorn col pass: zpart[b][j] = sum over 128 rows of A[i][j] r[i] ----------------
__global__ __launch_bounds__(256) void col_pass_kernel() {
    __shared__ double rs[128];
    int i0 = blockIdx.y * 128;
    if (threadIdx.x < 128) rs[threadIdx.x] = g_r[i0 + threadIdx.x];
    __syncthreads();
    int j = blockIdx.x * 512 + threadIdx.x * 2;
    const double* base = g_A + (size_t)i0 * NK + j;
    double s0 = 0.0, s1 = 0.0;
#pragma unroll 4
    for (int ii = 0; ii < 128; ii++) {
        double2 a = *(const double2*)(base + (size_t)ii * NK);
        double r = rs[ii];
        s0 += a.x * r;
        s1 += a.y * r;
    }
    double* zp = g_zpart + (size_t)blockIdx.y * NK + j;
    zp[0] = s0;
    zp[1] = s1;
}

__global__ __launch_bounds__(256) void col_update_kernel() {
    int j = blockIdx.x * blockDim.x + threadIdx.x;
    double z = 0.0;
#pragma unroll
    for (int b = 0; b < 64; b++) z += g_zpart[(size_t)b * NK + j];
    double c = g_c[j];
    g_c[j] = c / ((c * z) + 1e-8) / (double)NK;
}

// ---------------- probs output + argmax (tie -> lowest index, matching jnp.argmax) ----------------
__global__ __launch_bounds__(256) void probs_kernel(float* __restrict__ out_probs,
                                                    float* __restrict__ out_idx) {
    int i = blockIdx.x;
    const double* Arow = g_A + (size_t)i * NK;
    double R = 8192.0 * g_r[i];
    double best = -1.0;
    int bidx = 0x7FFFFFFF;
    float* orow = out_probs + (size_t)i * NK;
    for (int j = threadIdx.x; j < NK; j += 256) {
        double p = (R * Arow[j]) * g_c[j];
        orow[j] = (float)p;
        if (p > best) { best = p; bidx = j; }   // strict > keeps lowest j within thread
    }
    for (int o = 16; o; o >>= 1) {
        double ov = __shfl_down_sync(0xffffffffu, best, o);
        int oi = __shfl_down_sync(0xffffffffu, bidx, o);
        if (ov > best || (ov == best && oi < bidx)) { best = ov; bidx = oi; }
    }
    __shared__ double sv[8];
    __shared__ int si[8];
    if ((threadIdx.x & 31) == 0) { sv[threadIdx.x >> 5] = best; si[threadIdx.x >> 5] = bidx; }
    __syncthreads();
    if (threadIdx.x == 0) {
#pragma unroll
        for (int w = 1; w < 8; w++)
            if (sv[w] > best || (sv[w] == best && si[w] < bidx)) { best = sv[w]; bidx = si[w]; }
        g_idx[i] = bidx;
        out_idx[i] = (float)bidx;
    }
}

// ---------------- epilogue: quant_hard, quant_soft, loss ----------------
__global__ __launch_bounds__(128) void epilogue_kernel(const float* __restrict__ X,
                                                       const float* __restrict__ C,
                                                       float* __restrict__ qh,
                                                       float* __restrict__ qs,
                                                       float* __restrict__ loss) {
    int i = blockIdx.x;
    int idx = g_idx[i];
    const float4* cb = (const float4*)(C + (size_t)idx * ND);
    const float4* xr = (const float4*)(X + (size_t)i * ND);
    float4* oh = (float4*)(qh + (size_t)i * ND);
    float4* os = (float4*)(qs + (size_t)i * ND);
    int t = threadIdx.x;   // 128 threads * 4 = 512 = ND
    float4 c4 = cb[t];
    float4 x4 = xr[t];
    oh[t] = c4;
    float dx = c4.x - x4.x, dy = c4.y - x4.y, dz = c4.z - x4.z, dw = c4.w - x4.w;
    os[t] = make_float4(dx + x4.x, dy + x4.y, dz + x4.z, dw + x4.w);  // (qh-x)+x per ref
    double s = (double)dx * dx + (double)dy * dy + (double)dz * dz + (double)dw * dw;
    for (int o = 16; o; o >>= 1) s += __shfl_down_sync(0xffffffffu, s, o);
    __shared__ double sm[4];
    if ((t & 31) == 0) sm[t >> 5] = s;
    __syncthreads();
    if (t == 0) {
        double tot = (sm[0] + sm[1]) + (sm[2] + sm[3]);
        float cl = (float)(tot / (double)ND);
        loss[i] = cl + 0.25f * cl;   // codebook_loss + MU * commitment_loss (numerically equal)
    }
}

// ---------------- launch ----------------
extern "C" void kernel_launch(void* const* d_in, const int* in_sizes, int n_in,
                              void* d_out, int out_size) {
    const float* X = (const float*)d_in[0];
    const float* C = (const float*)d_in[1];
    float* out = (float*)d_out;
    float* o_qh    = out;
    float* o_qs    = out + (size_t)NB * ND;
    float* o_idx   = out + 2ULL * NB * ND;
    float* o_probs = o_idx + NB;
    float* o_loss  = o_probs + NM;

    reset_kernel<<<1, 32>>>();
    norms_kernel<<<dim3(NB, 2), 128>>>(X, C);
    gemm_kernel<<<dim3(64, 64), 256>>>(X, C);
    finalize_kernel<<<1, 1>>>();
    fill_kernel<<<2048, 256>>>();
    reduceS_kernel<<<1, 1024>>>();
    init_rc_kernel<<<32, 256>>>();
    for (int it = 0; it < 50; it++) {
        row_pass_kernel<<<NB, 256>>>();
        col_pass_kernel<<<dim3(16, 64), 256>>>();
        col_update_kernel<<<32, 256>>>();
    }
    probs_kernel<<<NB, 256>>>(o_probs, o_idx);
    epilogue_kernel<<<NB, 128>>>(X, C, o_qh, o_qs, o_loss);
}

// round 4
// speedup vs baseline: 2.3342x; 2.3342x over previous
#include <cuda_runtime.h>
#include <cuda_bf16.h>
#include <cstdint>

#define NB 8192
#define NK 8192
#define ND 512
#define NM (8192ULL * 8192ULL)

// ---------------- static device scratch ----------------
__device__ float  g_za[NM];         // log2(A) row-major (256 MB)
__device__ float  g_zaT[NM];        // log2(A) transposed (256 MB)
__device__ float  g_Dm[NM];         // d2 fp32 (256 MB)
__device__ float  g_nx[NB];
__device__ float  g_nc[NK];
__device__ double g_r[NB];
__device__ double g_c[NK];
__device__ float  g_zr[NB];         // log2(r)
__device__ float  g_zc[NK];         // log2(c)
__device__ double g_Spart[16384];
__device__ double g_S;
__device__ unsigned g_maxbits;
__device__ unsigned g_minbits;
__device__ float  g_midf;
__device__ float  g_rangef;
__device__ int    g_idx[NB];

__device__ __forceinline__ unsigned encf(float f) {
    unsigned u = __float_as_uint(f);
    return (u & 0x80000000u) ? ~u : (u | 0x80000000u);
}
__device__ __forceinline__ float decf(unsigned u) {
    return (u & 0x80000000u) ? __uint_as_float(u & 0x7FFFFFFFu) : __uint_as_float(~u);
}
// float log2 of a positive double (any exponent)
__device__ __forceinline__ float log2_of_double(double v) {
    int e; double m = frexp(v, &e);
    return (float)e + log2f((float)m);
}

// ---------------- reset (graph replays re-init) ----------------
__global__ void reset_kernel() {
    if (threadIdx.x == 0) {
        g_maxbits = 0u;
        g_minbits = 0xFFFFFFFFu;
    }
}

// ---------------- row norms ----------------
__global__ __launch_bounds__(128) void norms_kernel(const float* __restrict__ X,
                                                    const float* __restrict__ C) {
    int row = blockIdx.x;
    const float* p = (blockIdx.y == 0 ? X : C) + (size_t)row * ND;
    float4 v = ((const float4*)p)[threadIdx.x];
    double s = (double)v.x * v.x + (double)v.y * v.y + (double)v.z * v.z + (double)v.w * v.w;
    for (int o = 16; o; o >>= 1) s += __shfl_down_sync(0xffffffffu, s, o);
    __shared__ double sm[4];
    if ((threadIdx.x & 31) == 0) sm[threadIdx.x >> 5] = s;
    __syncthreads();
    if (threadIdx.x == 0) {
        double t = (sm[0] + sm[1]) + (sm[2] + sm[3]);
        if (blockIdx.y == 0) g_nx[row] = (float)t; else g_nc[row] = (float)t;
    }
}

// ---------------- fp32 GEMM -> d2, fused global min/max ----------------
__global__ __launch_bounds__(256) void gemm_kernel(const float* __restrict__ X,
                                                   const float* __restrict__ C) {
    __shared__ float As[16][132];
    __shared__ float Bs[16][132];
    const int tid = threadIdx.x;
    const int bi = blockIdx.y << 7;
    const int bj = blockIdx.x << 7;
    const int tr = (tid >> 4) << 3;
    const int tc = (tid & 15) << 3;
    const int lrow = tid >> 2;
    const int lk = (tid & 3) << 2;
    float acc[8][8];
#pragma unroll
    for (int p = 0; p < 8; p++)
#pragma unroll
        for (int q = 0; q < 8; q++) acc[p][q] = 0.f;

    for (int k0 = 0; k0 < ND; k0 += 16) {
#pragma unroll
        for (int rep = 0; rep < 2; rep++) {
            int r = lrow + (rep << 6);
            float4 va = *(const float4*)(X + (size_t)(bi + r) * ND + k0 + lk);
            As[lk + 0][r] = va.x; As[lk + 1][r] = va.y; As[lk + 2][r] = va.z; As[lk + 3][r] = va.w;
            float4 vb = *(const float4*)(C + (size_t)(bj + r) * ND + k0 + lk);
            Bs[lk + 0][r] = vb.x; Bs[lk + 1][r] = vb.y; Bs[lk + 2][r] = vb.z; Bs[lk + 3][r] = vb.w;
        }
        __syncthreads();
#pragma unroll
        for (int kk = 0; kk < 16; kk++) {
            float a[8], b[8];
#pragma unroll
            for (int p = 0; p < 8; p++) a[p] = As[kk][tr + p];
#pragma unroll
            for (int q = 0; q < 8; q++) b[q] = Bs[kk][tc + q];
#pragma unroll
            for (int p = 0; p < 8; p++)
#pragma unroll
                for (int q = 0; q < 8; q++) acc[p][q] += a[p] * b[q];
        }
        __syncthreads();
    }

    float nxv[8], ncv[8];
#pragma unroll
    for (int p = 0; p < 8; p++) nxv[p] = g_nx[bi + tr + p];
#pragma unroll
    for (int q = 0; q < 8; q++) ncv[q] = g_nc[bj + tc + q];
    float lmx = -3.4e38f, lmn = 3.4e38f;
#pragma unroll
    for (int p = 0; p < 8; p++) {
        float d2v[8];
#pragma unroll
        for (int q = 0; q < 8; q++) {
            float d2 = (nxv[p] + ncv[q]) - 2.0f * acc[p][q];
            d2v[q] = d2;
            lmx = fmaxf(lmx, d2);
            lmn = fminf(lmn, d2);
        }
        float* dst = g_Dm + (size_t)(bi + tr + p) * NK + bj + tc;
        *(float4*)(dst)     = make_float4(d2v[0], d2v[1], d2v[2], d2v[3]);
        *(float4*)(dst + 4) = make_float4(d2v[4], d2v[5], d2v[6], d2v[7]);
    }
    for (int o = 16; o; o >>= 1) {
        lmx = fmaxf(lmx, __shfl_down_sync(0xffffffffu, lmx, o));
        lmn = fminf(lmn, __shfl_down_sync(0xffffffffu, lmn, o));
    }
    __shared__ float smx[8], smn[8];
    if ((tid & 31) == 0) { smx[tid >> 5] = lmx; smn[tid >> 5] = lmn; }
    __syncthreads();
    if (tid == 0) {
#pragma unroll
        for (int w = 1; w < 8; w++) { lmx = fmaxf(lmx, smx[w]); lmn = fminf(lmn, smn[w]); }
        atomicMax(&g_maxbits, encf(lmx));
        atomicMin(&g_minbits, encf(lmn));
    }
}

__global__ void finalize_kernel() {
    float mx = decf(g_maxbits), mn = decf(g_minbits);
    float mid = (mx + mn) * 0.5f;
    g_midf = mid;
    g_rangef = (mx - mid) + 1e-8f;
}

// ---------------- fill: za = d2n * (-log2e/eps) fp32; write za + zaT; S partials ----------------
__global__ __launch_bounds__(256) void fill_kernel() {
    __shared__ float tile[64][65];
    __shared__ float sred[16];
    __shared__ float smb;
    const float midf = g_midf;
    const float rangef = g_rangef;
    const float cfh = -480.89834696298781f;
    const int tid = threadIdx.x;
    const int lane = tid & 31, warp = tid >> 5;
    const size_t i0 = (size_t)blockIdx.y * 64;
    const size_t j0 = (size_t)blockIdx.x * 64;
    const int r0 = tid >> 4;
    const int c4 = (tid & 15) << 2;

    float va[16];
    float mx = -3.4e38f;
#pragma unroll
    for (int k = 0; k < 4; k++) {
        int r = r0 + (k << 4);
        float4 d = *(const float4*)(g_Dm + (i0 + r) * NK + j0 + c4);
        float z0 = ((d.x - midf) / rangef) * cfh;
        float z1 = ((d.y - midf) / rangef) * cfh;
        float z2 = ((d.z - midf) / rangef) * cfh;
        float z3 = ((d.w - midf) / rangef) * cfh;
        va[k * 4 + 0] = z0; va[k * 4 + 1] = z1; va[k * 4 + 2] = z2; va[k * 4 + 3] = z3;
        tile[r][c4 + 0] = z0; tile[r][c4 + 1] = z1; tile[r][c4 + 2] = z2; tile[r][c4 + 3] = z3;
        *(float4*)(g_za + (i0 + r) * NK + j0 + c4) = make_float4(z0, z1, z2, z3);
        mx = fmaxf(mx, fmaxf(fmaxf(z0, z1), fmaxf(z2, z3)));
    }
    for (int o = 16; o; o >>= 1) mx = fmaxf(mx, __shfl_down_sync(0xffffffffu, mx, o));
    if (lane == 0) sred[warp] = mx;
    __syncthreads();
    if (tid == 0) {
        float m = sred[0];
#pragma unroll
        for (int w = 1; w < 8; w++) m = fmaxf(m, sred[w]);
        smb = floorf(m);
    }
    __syncthreads();
    const float mbf = smb;
    float s = 0.f;
#pragma unroll
    for (int k = 0; k < 16; k++) s += exp2f(va[k] - mbf);
    for (int o = 16; o; o >>= 1) s += __shfl_down_sync(0xffffffffu, s, o);
    if (lane == 0) sred[8 + warp] = s;
    __syncthreads();
    if (tid == 0) {
        float tot = 0.f;
#pragma unroll
        for (int w = 0; w < 8; w++) tot += sred[8 + w];
        g_Spart[blockIdx.y * 128 + blockIdx.x] = ldexp((double)tot, (int)mbf);
    }
#pragma unroll
    for (int k = 0; k < 4; k++) {
        int r = r0 + (k << 4);
        float4 v = make_float4(tile[c4 + 0][r], tile[c4 + 1][r], tile[c4 + 2][r], tile[c4 + 3][r]);
        *(float4*)(g_zaT + (j0 + r) * NK + i0 + c4) = v;
    }
}

__global__ __launch_bounds__(1024) void reduceS_kernel() {
    int tid = threadIdx.x;
    double s = 0.0;
#pragma unroll
    for (int k = 0; k < 16; k++) s += g_Spart[tid + k * 1024];
    __shared__ double sm[1024];
    sm[tid] = s;
    __syncthreads();
    for (int o = 512; o; o >>= 1) {
        if (tid < o) sm[tid] += sm[tid + o];
        __syncthreads();
    }
    if (tid == 0) g_S = sm[0];
}

__global__ void init_rc_kernel() {
    int t = blockIdx.x * blockDim.x + threadIdx.x;
    double S = g_S;
    if (t < NB) { g_r[t] = 1.0 / S; g_zr[t] = -log2_of_double(S); }
    if (t < NK) { g_c[t] = 1.0;     g_zc[t] = 0.0f; }
}

// ---------------- Sinkhorn pass (dir=0: row via g_za; dir=1: col via g_zaT) ----------------
// All device symbols resolved INSIDE device code (passing __device__ symbols as
// host-side kernel args reads the host shadow — silent garbage on GB300 ATS).
__global__ __launch_bounds__(256) void pass_kernel(int dir) {
    const float* __restrict__ ZA   = dir ? g_zaT : g_za;
    const float* __restrict__ zo   = dir ? g_zr  : g_zc;
    double* __restrict__      vec  = dir ? g_c   : g_r;
    float* __restrict__       zvec = dir ? g_zc  : g_zr;

    __shared__ float szo[NK];
    __shared__ float sred[16];
    __shared__ float sbc;
    const int tid = threadIdx.x;
    const int lane = tid & 31, warp = tid >> 5;
    for (int k = tid; k < NK / 4; k += 256)
        ((float4*)szo)[k] = ((const float4*)zo)[k];
    __syncthreads();
#pragma unroll 1
    for (int rr = 0; rr < 4; rr++) {
        const int i = (blockIdx.x << 2) + rr;
        const float4* a4 = (const float4*)(ZA + (size_t)i * NK);
        const float4* c4s = (const float4*)szo;
        float t[32];
        float mx = -3.4e38f;
#pragma unroll
        for (int k = 0; k < 8; k++) {
            int j4 = tid + (k << 8);
            float4 a = a4[j4];
            float4 c = c4s[j4];
            float t0 = a.x + c.x, t1 = a.y + c.y, t2 = a.z + c.z, t3 = a.w + c.w;
            t[k * 4 + 0] = t0; t[k * 4 + 1] = t1; t[k * 4 + 2] = t2; t[k * 4 + 3] = t3;
            mx = fmaxf(mx, fmaxf(fmaxf(t0, t1), fmaxf(t2, t3)));
        }
        for (int o = 16; o; o >>= 1) mx = fmaxf(mx, __shfl_down_sync(0xffffffffu, mx, o));
        if (lane == 0) sred[warp] = mx;
        __syncthreads();
        if (tid == 0) {
            float m = sred[0];
#pragma unroll
            for (int w = 1; w < 8; w++) m = fmaxf(m, sred[w]);
            sbc = floorf(m);
        }
        __syncthreads();
        const float mf = sbc;
        float s0 = 0.f, s1 = 0.f, s2 = 0.f, s3 = 0.f;
#pragma unroll
        for (int k = 0; k < 8; k++) {
            s0 += exp2f(t[k * 4 + 0] - mf);
            s1 += exp2f(t[k * 4 + 1] - mf);
            s2 += exp2f(t[k * 4 + 2] - mf);
            s3 += exp2f(t[k * 4 + 3] - mf);
        }
        float ss = (s0 + s1) + (s2 + s3);
        for (int o = 16; o; o >>= 1) ss += __shfl_down_sync(0xffffffffu, ss, o);
        if (lane == 0) sred[8 + warp] = ss;
        __syncthreads();
        if (tid == 0) {
            float tot = 0.f;
#pragma unroll
            for (int w = 0; w < 8; w++) tot += sred[8 + w];
            double y = ldexp((double)tot, (int)mf);
            double v = vec[i];
            double vn = v / ((v * y) + 1e-8) / 8192.0;
            vec[i] = vn;
            zvec[i] = log2_of_double(vn);
        }
        __syncthreads();
    }
}

// ---------------- probs + argmax ----------------
__global__ __launch_bounds__(256) void probs_kernel(float* __restrict__ out_probs,
                                                    float* __restrict__ out_idx) {
    __shared__ float szc[NK];
    __shared__ float sred[8];
    __shared__ int sidx[8];
    const int tid = threadIdx.x;
    const int lane = tid & 31, warp = tid >> 5;
    for (int k = tid; k < NK / 4; k += 256)
        ((float4*)szc)[k] = ((const float4*)g_zc)[k];
    __syncthreads();
#pragma unroll 1
    for (int rr = 0; rr < 4; rr++) {
        const int i = (blockIdx.x << 2) + rr;
        const float lR = log2_of_double(8192.0 * g_r[i]);
        const float4* a4 = (const float4*)(g_za + (size_t)i * NK);
        float4* o4 = (float4*)(out_probs + (size_t)i * NK);
        float best = -3.4e38f; int bj = 0x7FFFFFFF;
#pragma unroll
        for (int k = 0; k < 8; k++) {
            int j4 = tid + (k << 8);
            float4 a = a4[j4];
            float4 c = ((const float4*)szc)[j4];
            float t0 = a.x + c.x, t1 = a.y + c.y, t2 = a.z + c.z, t3 = a.w + c.w;
            o4[j4] = make_float4(exp2f(t0 + lR), exp2f(t1 + lR), exp2f(t2 + lR), exp2f(t3 + lR));
            int jb = j4 << 2;
            if (t0 > best) { best = t0; bj = jb; }
            if (t1 > best) { best = t1; bj = jb + 1; }
            if (t2 > best) { best = t2; bj = jb + 2; }
            if (t3 > best) { best = t3; bj = jb + 3; }
        }
        for (int o = 16; o; o >>= 1) {
            float ov = __shfl_down_sync(0xffffffffu, best, o);
            int oi = __shfl_down_sync(0xffffffffu, bj, o);
            if (ov > best || (ov == best && oi < bj)) { best = ov; bj = oi; }
        }
        if (lane == 0) { sred[warp] = best; sidx[warp] = bj; }
        __syncthreads();
        if (tid == 0) {
#pragma unroll
            for (int w = 1; w < 8; w++)
                if (sred[w] > best || (sred[w] == best && sidx[w] < bj)) { best = sred[w]; bj = sidx[w]; }
            g_idx[i] = bj;
            out_idx[i] = (float)bj;
        }
        __syncthreads();
    }
}

// ---------------- epilogue ----------------
__global__ __launch_bounds__(128) void epilogue_kernel(const float* __restrict__ X,
                                                       const float* __restrict__ C,
                                                       float* __restrict__ qh,
                                                       float* __restrict__ qs,
                                                       float* __restrict__ loss) {
    int i = blockIdx.x;
    int idx = g_idx[i];
    const float4* cb = (const float4*)(C + (size_t)idx * ND);
    const float4* xr = (const float4*)(X + (size_t)i * ND);
    float4* oh = (float4*)(qh + (size_t)i * ND);
    float4* os = (float4*)(qs + (size_t)i * ND);
    int t = threadIdx.x;
    float4 c4 = cb[t];
    float4 x4 = xr[t];
    oh[t] = c4;
    float dx = c4.x - x4.x, dy = c4.y - x4.y, dz = c4.z - x4.z, dw = c4.w - x4.w;
    os[t] = make_float4(dx + x4.x, dy + x4.y, dz + x4.z, dw + x4.w);
    double s = (double)dx * dx + (double)dy * dy + (double)dz * dz + (double)dw * dw;
    for (int o = 16; o; o >>= 1) s += __shfl_down_sync(0xffffffffu, s, o);
    __shared__ double sm[4];
    if ((t & 31) == 0) sm[t >> 5] = s;
    __syncthreads();
    if (t == 0) {
        double tot = (sm[0] + sm[1]) + (sm[2] + sm[3]);
        float cl = (float)(tot / (double)ND);
        loss[i] = cl + 0.25f * cl;
    }
}

// ---------------- launch ----------------
extern "C" void kernel_launch(void* const* d_in, const int* in_sizes, int n_in,
                              void* d_out, int out_size) {
    const float* X = (const float*)d_in[0];
    const float* C = (const float*)d_in[1];
    float* out = (float*)d_out;
    float* o_qh    = out;
    float* o_qs    = out + (size_t)NB * ND;
    float* o_idx   = out + 2ULL * NB * ND;
    float* o_probs = o_idx + NB;
    float* o_loss  = o_probs + NM;

    reset_kernel<<<1, 32>>>();
    norms_kernel<<<dim3(NB, 2), 128>>>(X, C);
    gemm_kernel<<<dim3(64, 64), 256>>>(X, C);
    finalize_kernel<<<1, 1>>>();
    fill_kernel<<<dim3(128, 128), 256>>>();
    reduceS_kernel<<<1, 1024>>>();
    init_rc_kernel<<<32, 256>>>();
    for (int it = 0; it < 50; it++) {
        pass_kernel<<<2048, 256>>>(0);   // row normalize
        pass_kernel<<<2048, 256>>>(1);   // col normalize
    }
    probs_kernel<<<2048, 256>>>(o_probs, o_idx);
    epilogue_kernel<<<NB, 128>>>(X, C, o_qh, o_qs, o_loss);
}

// round 5
// speedup vs baseline: 2.3364x; 1.0009x over previous
#include <cuda_runtime.h>
#include <cuda_bf16.h>
#include <cstdint>

#define NB 8192
#define NK 8192
#define ND 512
#define NM (8192ULL * 8192ULL)

// ---------------- static device scratch ----------------
__device__ float  g_za[NM];         // log2(A) row-major (256 MB)
__device__ float  g_zaT[NM];        // log2(A) transposed (256 MB)
__device__ float  g_Dm[NM];         // d2 fp32 (256 MB)
__device__ float  g_nx[NB];
__device__ float  g_nc[NK];
__device__ double g_r[NB];
__device__ double g_c[NK];
__device__ float  g_zr[NB];         // log2(r)
__device__ float  g_zc[NK];         // log2(c)
__device__ double g_Spart[16384];
__device__ double g_S;
__device__ unsigned g_maxbits;
__device__ unsigned g_minbits;
__device__ float  g_midf;
__device__ float  g_rangef;
__device__ int    g_idx[NB];

__device__ __forceinline__ unsigned encf(float f) {
    unsigned u = __float_as_uint(f);
    return (u & 0x80000000u) ? ~u : (u | 0x80000000u);
}
__device__ __forceinline__ float decf(unsigned u) {
    return (u & 0x80000000u) ? __uint_as_float(u & 0x7FFFFFFFu) : __uint_as_float(~u);
}
// float log2 of a positive double (any exponent)
__device__ __forceinline__ float log2_of_double(double v) {
    int e; double m = frexp(v, &e);
    return (float)e + log2f((float)m);
}

// ---------------- reset (graph replays re-init) ----------------
__global__ void reset_kernel() {
    if (threadIdx.x == 0) {
        g_maxbits = 0u;
        g_minbits = 0xFFFFFFFFu;
    }
}

// ---------------- row norms ----------------
__global__ __launch_bounds__(128) void norms_kernel(const float* __restrict__ X,
                                                    const float* __restrict__ C) {
    int row = blockIdx.x;
    const float* p = (blockIdx.y == 0 ? X : C) + (size_t)row * ND;
    float4 v = ((const float4*)p)[threadIdx.x];
    double s = (double)v.x * v.x + (double)v.y * v.y + (double)v.z * v.z + (double)v.w * v.w;
    for (int o = 16; o; o >>= 1) s += __shfl_down_sync(0xffffffffu, s, o);
    __shared__ double sm[4];
    if ((threadIdx.x & 31) == 0) sm[threadIdx.x >> 5] = s;
    __syncthreads();
    if (threadIdx.x == 0) {
        double t = (sm[0] + sm[1]) + (sm[2] + sm[3]);
        if (blockIdx.y == 0) g_nx[row] = (float)t; else g_nc[row] = (float)t;
    }
}

// ---------------- fp32 GEMM -> d2, fused global min/max ----------------
__global__ __launch_bounds__(256) void gemm_kernel(const float* __restrict__ X,
                                                   const float* __restrict__ C) {
    __shared__ float As[16][132];
    __shared__ float Bs[16][132];
    const int tid = threadIdx.x;
    const int bi = blockIdx.y << 7;
    const int bj = blockIdx.x << 7;
    const int tr = (tid >> 4) << 3;
    const int tc = (tid & 15) << 3;
    const int lrow = tid >> 2;
    const int lk = (tid & 3) << 2;
    float acc[8][8];
#pragma unroll
    for (int p = 0; p < 8; p++)
#pragma unroll
        for (int q = 0; q < 8; q++) acc[p][q] = 0.f;

    for (int k0 = 0; k0 < ND; k0 += 16) {
#pragma unroll
        for (int rep = 0; rep < 2; rep++) {
            int r = lrow + (rep << 6);
            float4 va = *(const float4*)(X + (size_t)(bi + r) * ND + k0 + lk);
            As[lk + 0][r] = va.x; As[lk + 1][r] = va.y; As[lk + 2][r] = va.z; As[lk + 3][r] = va.w;
            float4 vb = *(const float4*)(C + (size_t)(bj + r) * ND + k0 + lk);
            Bs[lk + 0][r] = vb.x; Bs[lk + 1][r] = vb.y; Bs[lk + 2][r] = vb.z; Bs[lk + 3][r] = vb.w;
        }
        __syncthreads();
#pragma unroll
        for (int kk = 0; kk < 16; kk++) {
            float a[8], b[8];
#pragma unroll
            for (int p = 0; p < 8; p++) a[p] = As[kk][tr + p];
#pragma unroll
            for (int q = 0; q < 8; q++) b[q] = Bs[kk][tc + q];
#pragma unroll
            for (int p = 0; p < 8; p++)
#pragma unroll
                for (int q = 0; q < 8; q++) acc[p][q] += a[p] * b[q];
        }
        __syncthreads();
    }

    float nxv[8], ncv[8];
#pragma unroll
    for (int p = 0; p < 8; p++) nxv[p] = g_nx[bi + tr + p];
#pragma unroll
    for (int q = 0; q < 8; q++) ncv[q] = g_nc[bj + tc + q];
    float lmx = -3.4e38f, lmn = 3.4e38f;
#pragma unroll
    for (int p = 0; p < 8; p++) {
        float d2v[8];
#pragma unroll
        for (int q = 0; q < 8; q++) {
            float d2 = (nxv[p] + ncv[q]) - 2.0f * acc[p][q];
            d2v[q] = d2;
            lmx = fmaxf(lmx, d2);
            lmn = fminf(lmn, d2);
        }
        float* dst = g_Dm + (size_t)(bi + tr + p) * NK + bj + tc;
        *(float4*)(dst)     = make_float4(d2v[0], d2v[1], d2v[2], d2v[3]);
        *(float4*)(dst + 4) = make_float4(d2v[4], d2v[5], d2v[6], d2v[7]);
    }
    for (int o = 16; o; o >>= 1) {
        lmx = fmaxf(lmx, __shfl_down_sync(0xffffffffu, lmx, o));
        lmn = fminf(lmn, __shfl_down_sync(0xffffffffu, lmn, o));
    }
    __shared__ float smx[8], smn[8];
    if ((tid & 31) == 0) { smx[tid >> 5] = lmx; smn[tid >> 5] = lmn; }
    __syncthreads();
    if (tid == 0) {
#pragma unroll
        for (int w = 1; w < 8; w++) { lmx = fmaxf(lmx, smx[w]); lmn = fminf(lmn, smn[w]); }
        atomicMax(&g_maxbits, encf(lmx));
        atomicMin(&g_minbits, encf(lmn));
    }
}

__global__ void finalize_kernel() {
    float mx = decf(g_maxbits), mn = decf(g_minbits);
    float mid = (mx + mn) * 0.5f;
    g_midf = mid;
    g_rangef = (mx - mid) + 1e-8f;
}

// ---------------- fill: za = d2n * (-log2e/eps) fp32; write za + zaT; S partials ----------------
__global__ __launch_bounds__(256) void fill_kernel() {
    __shared__ float tile[64][65];
    __shared__ float sred[16];
    __shared__ float smb;
    const float midf = g_midf;
    const float rangef = g_rangef;
    const float cfh = -480.89834696298781f;
    const int tid = threadIdx.x;
    const int lane = tid & 31, warp = tid >> 5;
    const size_t i0 = (size_t)blockIdx.y * 64;
    const size_t j0 = (size_t)blockIdx.x * 64;
    const int r0 = tid >> 4;
    const int c4 = (tid & 15) << 2;

    float va[16];
    float mx = -3.4e38f;
#pragma unroll
    for (int k = 0; k < 4; k++) {
        int r = r0 + (k << 4);
        float4 d = *(const float4*)(g_Dm + (i0 + r) * NK + j0 + c4);
        float z0 = ((d.x - midf) / rangef) * cfh;
        float z1 = ((d.y - midf) / rangef) * cfh;
        float z2 = ((d.z - midf) / rangef) * cfh;
        float z3 = ((d.w - midf) / rangef) * cfh;
        va[k * 4 + 0] = z0; va[k * 4 + 1] = z1; va[k * 4 + 2] = z2; va[k * 4 + 3] = z3;
        tile[r][c4 + 0] = z0; tile[r][c4 + 1] = z1; tile[r][c4 + 2] = z2; tile[r][c4 + 3] = z3;
        *(float4*)(g_za + (i0 + r) * NK + j0 + c4) = make_float4(z0, z1, z2, z3);
        mx = fmaxf(mx, fmaxf(fmaxf(z0, z1), fmaxf(z2, z3)));
    }
    for (int o = 16; o; o >>= 1) mx = fmaxf(mx, __shfl_down_sync(0xffffffffu, mx, o));
    if (lane == 0) sred[warp] = mx;
    __syncthreads();
    if (tid == 0) {
        float m = sred[0];
#pragma unroll
        for (int w = 1; w < 8; w++) m = fmaxf(m, sred[w]);
        smb = floorf(m);
    }
    __syncthreads();
    const float mbf = smb;
    float s = 0.f;
#pragma unroll
    for (int k = 0; k < 16; k++) s += exp2f(va[k] - mbf);
    for (int o = 16; o; o >>= 1) s += __shfl_down_sync(0xffffffffu, s, o);
    if (lane == 0) sred[8 + warp] = s;
    __syncthreads();
    if (tid == 0) {
        float tot = 0.f;
#pragma unroll
        for (int w = 0; w < 8; w++) tot += sred[8 + w];
        g_Spart[blockIdx.y * 128 + blockIdx.x] = ldexp((double)tot, (int)mbf);
    }
#pragma unroll
    for (int k = 0; k < 4; k++) {
        int r = r0 + (k << 4);
        float4 v = make_float4(tile[c4 + 0][r], tile[c4 + 1][r], tile[c4 + 2][r], tile[c4 + 3][r]);
        *(float4*)(g_zaT + (j0 + r) * NK + i0 + c4) = v;
    }
}

__global__ __launch_bounds__(1024) void reduceS_kernel() {
    int tid = threadIdx.x;
    double s = 0.0;
#pragma unroll
    for (int k = 0; k < 16; k++) s += g_Spart[tid + k * 1024];
    __shared__ double sm[1024];
    sm[tid] = s;
    __syncthreads();
    for (int o = 512; o; o >>= 1) {
        if (tid < o) sm[tid] += sm[tid + o];
        __syncthreads();
    }
    if (tid == 0) g_S = sm[0];
}

__global__ void init_rc_kernel() {
    int t = blockIdx.x * blockDim.x + threadIdx.x;
    double S = g_S;
    if (t < NB) { g_r[t] = 1.0 / S; g_zr[t] = -log2_of_double(S); }
    if (t < NK) { g_c[t] = 1.0;     g_zc[t] = 0.0f; }
}

// ---------------- Sinkhorn pass (dir=0: row via g_za; dir=1: col via g_zaT) ----------------
// All device symbols resolved INSIDE device code (passing __device__ symbols as
// host-side kernel args reads the host shadow — silent garbage on GB300 ATS).
__global__ __launch_bounds__(256) void pass_kernel(int dir) {
    const float* __restrict__ ZA   = dir ? g_zaT : g_za;
    const float* __restrict__ zo   = dir ? g_zr  : g_zc;
    double* __restrict__      vec  = dir ? g_c   : g_r;
    float* __restrict__       zvec = dir ? g_zc  : g_zr;

    __shared__ float szo[NK];
    __shared__ float sred[16];
    __shared__ float sbc;
    const int tid = threadIdx.x;
    const int lane = tid & 31, warp = tid >> 5;
    for (int k = tid; k < NK / 4; k += 256)
        ((float4*)szo)[k] = ((const float4*)zo)[k];
    __syncthreads();
#pragma unroll 1
    for (int rr = 0; rr < 4; rr++) {
        const int i = (blockIdx.x << 2) + rr;
        const float4* a4 = (const float4*)(ZA + (size_t)i * NK);
        const float4* c4s = (const float4*)szo;
        float t[32];
        float mx = -3.4e38f;
#pragma unroll
        for (int k = 0; k < 8; k++) {
            int j4 = tid + (k << 8);
            float4 a = a4[j4];
            float4 c = c4s[j4];
            float t0 = a.x + c.x, t1 = a.y + c.y, t2 = a.z + c.z, t3 = a.w + c.w;
            t[k * 4 + 0] = t0; t[k * 4 + 1] = t1; t[k * 4 + 2] = t2; t[k * 4 + 3] = t3;
            mx = fmaxf(mx, fmaxf(fmaxf(t0, t1), fmaxf(t2, t3)));
        }
        for (int o = 16; o; o >>= 1) mx = fmaxf(mx, __shfl_down_sync(0xffffffffu, mx, o));
        if (lane == 0) sred[warp] = mx;
        __syncthreads();
        if (tid == 0) {
            float m = sred[0];
#pragma unroll
            for (int w = 1; w < 8; w++) m = fmaxf(m, sred[w]);
            sbc = floorf(m);
        }
        __syncthreads();
        const float mf = sbc;
        float s0 = 0.f, s1 = 0.f, s2 = 0.f, s3 = 0.f;
#pragma unroll
        for (int k = 0; k < 8; k++) {
            s0 += exp2f(t[k * 4 + 0] - mf);
            s1 += exp2f(t[k * 4 + 1] - mf);
            s2 += exp2f(t[k * 4 + 2] - mf);
            s3 += exp2f(t[k * 4 + 3] - mf);
        }
        float ss = (s0 + s1) + (s2 + s3);
        for (int o = 16; o; o >>= 1) ss += __shfl_down_sync(0xffffffffu, ss, o);
        if (lane == 0) sred[8 + warp] = ss;
        __syncthreads();
        if (tid == 0) {
            float tot = 0.f;
#pragma unroll
            for (int w = 0; w < 8; w++) tot += sred[8 + w];
            double y = ldexp((double)tot, (int)mf);
            double v = vec[i];
            double vn = v / ((v * y) + 1e-8) / 8192.0;
            vec[i] = vn;
            zvec[i] = log2_of_double(vn);
        }
        __syncthreads();
    }
}

// ---------------- probs + argmax ----------------
__global__ __launch_bounds__(256) void probs_kernel(float* __restrict__ out_probs,
                                                    float* __restrict__ out_idx) {
    __shared__ float szc[NK];
    __shared__ float sred[8];
    __shared__ int sidx[8];
    const int tid = threadIdx.x;
    const int lane = tid & 31, warp = tid >> 5;
    for (int k = tid; k < NK / 4; k += 256)
        ((float4*)szc)[k] = ((const float4*)g_zc)[k];
    __syncthreads();
#pragma unroll 1
    for (int rr = 0; rr < 4; rr++) {
        const int i = (blockIdx.x << 2) + rr;
        const float lR = log2_of_double(8192.0 * g_r[i]);
        const float4* a4 = (const float4*)(g_za + (size_t)i * NK);
        float4* o4 = (float4*)(out_probs + (size_t)i * NK);
        float best = -3.4e38f; int bj = 0x7FFFFFFF;
#pragma unroll
        for (int k = 0; k < 8; k++) {
            int j4 = tid + (k << 8);
            float4 a = a4[j4];
            float4 c = ((const float4*)szc)[j4];
            float t0 = a.x + c.x, t1 = a.y + c.y, t2 = a.z + c.z, t3 = a.w + c.w;
            o4[j4] = make_float4(exp2f(t0 + lR), exp2f(t1 + lR), exp2f(t2 + lR), exp2f(t3 + lR));
            int jb = j4 << 2;
            if (t0 > best) { best = t0; bj = jb; }
            if (t1 > best) { best = t1; bj = jb + 1; }
            if (t2 > best) { best = t2; bj = jb + 2; }
            if (t3 > best) { best = t3; bj = jb + 3; }
        }
        for (int o = 16; o; o >>= 1) {
            float ov = __shfl_down_sync(0xffffffffu, best, o);
            int oi = __shfl_down_sync(0xffffffffu, bj, o);
            if (ov > best || (ov == best && oi < bj)) { best = ov; bj = oi; }
        }
        if (lane == 0) { sred[warp] = best; sidx[warp] = bj; }
        __syncthreads();
        if (tid == 0) {
#pragma unroll
            for (int w = 1; w < 8; w++)
                if (sred[w] > best || (sred[w] == best && sidx[w] < bj)) { best = sred[w]; bj = sidx[w]; }
            g_idx[i] = bj;
            out_idx[i] = (float)bj;
        }
        __syncthreads();
    }
}

// ---------------- epilogue ----------------
__global__ __launch_bounds__(128) void epilogue_kernel(const float* __restrict__ X,
                                                       const float* __restrict__ C,
                                                       float* __restrict__ qh,
                                                       float* __restrict__ qs,
                                                       float* __restrict__ loss) {
    int i = blockIdx.x;
    int idx = g_idx[i];
    const float4* cb = (const float4*)(C + (size_t)idx * ND);
    const float4* xr = (const float4*)(X + (size_t)i * ND);
    float4* oh = (float4*)(qh + (size_t)i * ND);
    float4* os = (float4*)(qs + (size_t)i * ND);
    int t = threadIdx.x;
    float4 c4 = cb[t];
    float4 x4 = xr[t];
    oh[t] = c4;
    float dx = c4.x - x4.x, dy = c4.y - x4.y, dz = c4.z - x4.z, dw = c4.w - x4.w;
    os[t] = make_float4(dx + x4.x, dy + x4.y, dz + x4.z, dw + x4.w);
    double s = (double)dx * dx + (double)dy * dy + (double)dz * dz + (double)dw * dw;
    for (int o = 16; o; o >>= 1) s += __shfl_down_sync(0xffffffffu, s, o);
    __shared__ double sm[4];
    if ((t & 31) == 0) sm[t >> 5] = s;
    __syncthreads();
    if (t == 0) {
        double tot = (sm[0] + sm[1]) + (sm[2] + sm[3]);
        float cl = (float)(tot / (double)ND);
        loss[i] = cl + 0.25f * cl;
    }
}

// ---------------- launch ----------------
extern "C" void kernel_launch(void* const* d_in, const int* in_sizes, int n_in,
                              void* d_out, int out_size) {
    const float* X = (const float*)d_in[0];
    const float* C = (const float*)d_in[1];
    float* out = (float*)d_out;
    float* o_qh    = out;
    float* o_qs    = out + (size_t)NB * ND;
    float* o_idx   = out + 2ULL * NB * ND;
    float* o_probs = o_idx + NB;
    float* o_loss  = o_probs + NM;

    reset_kernel<<<1, 32>>>();
    norms_kernel<<<dim3(NB, 2), 128>>>(X, C);
    gemm_kernel<<<dim3(64, 64), 256>>>(X, C);
    finalize_kernel<<<1, 1>>>();
    fill_kernel<<<dim3(128, 128), 256>>>();
    reduceS_kernel<<<1, 1024>>>();
    init_rc_kernel<<<32, 256>>>();
    for (int it = 0; it < 50; it++) {
        pass_kernel<<<2048, 256>>>(0);   // row normalize
        pass_kernel<<<2048, 256>>>(1);   // col normalize
    }
    probs_kernel<<<2048, 256>>>(o_probs, o_idx);
    epilogue_kernel<<<NB, 128>>>(X, C, o_qh, o_qs, o_loss);
}

// round 6
// speedup vs baseline: 2.5984x; 1.1122x over previous
#include <cuda_runtime.h>
#include <cuda_bf16.h>
#include <cstdint>

#define NB 8192
#define NK 8192
#define ND 512
#define NM (8192ULL * 8192ULL)
#define GK 1536

// ---------------- static device scratch ----------------
__device__ float  g_za[NM];
__device__ float  g_zaT[NM];
__device__ float  g_Dm[NM];
__device__ __nv_bfloat16 g_Xe[8192ULL * GK];  // [x1|x1|x2]
__device__ __nv_bfloat16 g_Ce[8192ULL * GK];  // [c1|c2|c1]
__device__ float  g_nx[NB];
__device__ float  g_nc[NK];
__device__ double g_r[NB];
__device__ double g_c[NK];
__device__ float  g_zr[NB];
__device__ float  g_zc[NK];
__device__ double g_Spart[16384];
__device__ double g_S;
__device__ unsigned g_maxbits;
__device__ unsigned g_minbits;
__device__ float  g_midf;
__device__ float  g_rangef;
__device__ int    g_idx[NB];

__device__ __forceinline__ unsigned encf(float f) {
    unsigned u = __float_as_uint(f);
    return (u & 0x80000000u) ? ~u : (u | 0x80000000u);
}
__device__ __forceinline__ float decf(unsigned u) {
    return (u & 0x80000000u) ? __uint_as_float(u & 0x7FFFFFFFu) : __uint_as_float(~u);
}
__device__ __forceinline__ float log2_of_double(double v) {
    int e; double m = frexp(v, &e);
    return (float)e + log2f((float)m);
}
__device__ __forceinline__ uint32_t smem_u32(const void* p) {
    uint32_t a;
    asm("{ .reg .u64 t; cvta.to.shared.u64 t, %1; cvt.u32.u64 %0, t; }" : "=r"(a) : "l"(p));
    return a;
}
__device__ __forceinline__ void cpa16(uint32_t s, const void* g) {
    asm volatile("cp.async.cg.shared.global [%0], [%1], 16;" :: "r"(s), "l"(g) : "memory");
}
#define CPA_COMMIT() asm volatile("cp.async.commit_group;" ::: "memory")
template <int N> __device__ __forceinline__ void cpa_wait() {
    asm volatile("cp.async.wait_group %0;" :: "n"(N) : "memory");
}
__device__ __forceinline__ void ldsm4(uint32_t* r, uint32_t addr) {
    asm volatile("ldmatrix.sync.aligned.m8n8.x4.shared.b16 {%0,%1,%2,%3}, [%4];"
        : "=r"(r[0]), "=r"(r[1]), "=r"(r[2]), "=r"(r[3]) : "r"(addr));
}
__device__ __forceinline__ void mma16816(float* d, const uint32_t* a, uint32_t b0, uint32_t b1) {
    asm volatile("mma.sync.aligned.m16n8k16.row.col.f32.bf16.bf16.f32 "
        "{%0,%1,%2,%3}, {%4,%5,%6,%7}, {%8,%9}, {%0,%1,%2,%3};"
        : "+f"(d[0]), "+f"(d[1]), "+f"(d[2]), "+f"(d[3])
        : "r"(a[0]), "r"(a[1]), "r"(a[2]), "r"(a[3]), "r"(b0), "r"(b1));
}

// ---------------- reset ----------------
__global__ void reset_kernel() {
    if (threadIdx.x == 0) { g_maxbits = 0u; g_minbits = 0xFFFFFFFFu; }
}

// ---------------- row norms ----------------
__global__ __launch_bounds__(128) void norms_kernel(const float* __restrict__ X,
                                                    const float* __restrict__ C) {
    int row = blockIdx.x;
    const float* p = (blockIdx.y == 0 ? X : C) + (size_t)row * ND;
    float4 v = ((const float4*)p)[threadIdx.x];
    double s = (double)v.x * v.x + (double)v.y * v.y + (double)v.z * v.z + (double)v.w * v.w;
    for (int o = 16; o; o >>= 1) s += __shfl_down_sync(0xffffffffu, s, o);
    __shared__ double sm[4];
    if ((threadIdx.x & 31) == 0) sm[threadIdx.x >> 5] = s;
    __syncthreads();
    if (threadIdx.x == 0) {
        double t = (sm[0] + sm[1]) + (sm[2] + sm[3]);
        if (blockIdx.y == 0) g_nx[row] = (float)t; else g_nc[row] = (float)t;
    }
}

// ---------------- split-bf16 prep ----------------
__global__ __launch_bounds__(256) void split_kernel(const float* __restrict__ X,
                                                    const float* __restrict__ C) {
    size_t idx = (size_t)blockIdx.x * 256 + threadIdx.x;
    size_t row = idx >> 9, k = idx & 511;
    {
        float x = X[idx];
        __nv_bfloat16 b1 = __float2bfloat16(x);
        __nv_bfloat16 b2 = __float2bfloat16(x - __bfloat162float(b1));
        __nv_bfloat16* d = g_Xe + row * GK + k;
        d[0] = b1; d[512] = b1; d[1024] = b2;
    }
    {
        float c = C[idx];
        __nv_bfloat16 b1 = __float2bfloat16(c);
        __nv_bfloat16 b2 = __float2bfloat16(c - __bfloat162float(b1));
        __nv_bfloat16* d = g_Ce + row * GK + k;
        d[0] = b1; d[512] = b2; d[1024] = b1;
    }
}

// ---------------- tensor-core GEMM: d2 = nx+nc-2*(Xe@Ce^T), fused minmax ----------------
// 128x128 tile, 256 threads (4x2 warps of 32x64), K-chunk 32, double-buffered cp.async.
#define SPITCH 40            // bf16 elements per smem row (80B, conflict-free)
#define SBUF   (128 * SPITCH)  // elements per buffer

__global__ __launch_bounds__(256) void mma_gemm_kernel() {
    __shared__ __nv_bfloat16 sA[2 * SBUF];
    __shared__ __nv_bfloat16 sB[2 * SBUF];
    const int tid = threadIdx.x;
    const int lane = tid & 31, wid = tid >> 5;
    const int wm = wid & 3, wn = wid >> 2;
    const int bi = blockIdx.y << 7, bj = blockIdx.x << 7;
    const uint32_t sAu = smem_u32(sA), sBu = smem_u32(sB);
    const __nv_bfloat16* Ag = g_Xe + (size_t)bi * GK;
    const __nv_bfloat16* Bg = g_Ce + (size_t)bj * GK;
    const int lrow = tid >> 2, lseg = (tid & 3) << 3;   // 64 cols = 8 segs? no: 4 segs of 8

    float acc[2][8][4];
#pragma unroll
    for (int t = 0; t < 2; t++)
#pragma unroll
        for (int u = 0; u < 8; u++)
#pragma unroll
            for (int v = 0; v < 4; v++) acc[t][u][v] = 0.f;

#define LOAD_CHUNK(c, buf)                                                          \
    {                                                                               \
        _Pragma("unroll")                                                           \
        for (int t = 0; t < 2; t++) {                                               \
            int s = tid + (t << 8);                                                 \
            int r = s >> 2, sg = (s & 3) << 3;                                      \
            uint32_t so = (buf) * (SBUF * 2) + r * (SPITCH * 2) + sg * 2;           \
            const size_t go = (size_t)r * GK + (c) * 32 + sg;                       \
            cpa16(sAu + so, Ag + go);                                               \
            cpa16(sBu + so, Bg + go);                                               \
        }                                                                           \
    }

    LOAD_CHUNK(0, 0);
    CPA_COMMIT();

    // ldmatrix address components
    const uint32_t aRowOff = (uint32_t)(wm * 32 + (lane & 15)) * (SPITCH * 2);
    const uint32_t aColOff = (uint32_t)((lane >> 4) << 3) * 2;
    const uint32_t bRowBase = (uint32_t)(wn * 64 + (lane & 7) + (((lane >> 4) & 1) << 3));
    const uint32_t bColOff = (uint32_t)(((lane >> 3) & 1) << 3) * 2;

    for (int c = 0; c < GK / 32; c++) {
        int buf = c & 1;
        if (c + 1 < GK / 32) LOAD_CHUNK(c + 1, buf ^ 1);
        CPA_COMMIT();
        cpa_wait<1>();
        __syncthreads();
        uint32_t abase = sAu + buf * (SBUF * 2);
        uint32_t bbase = sBu + buf * (SBUF * 2);
#pragma unroll
        for (int kk = 0; kk < 2; kk++) {
            uint32_t a[2][4], b[4][4];
#pragma unroll
            for (int t = 0; t < 2; t++)
                ldsm4(a[t], abase + aRowOff + (uint32_t)(t * 16) * (SPITCH * 2)
                            + aColOff + (uint32_t)(kk * 16) * 2);
#pragma unroll
            for (int p = 0; p < 4; p++)
                ldsm4(b[p], bbase + (bRowBase + p * 16) * (SPITCH * 2)
                            + bColOff + (uint32_t)(kk * 16) * 2);
#pragma unroll
            for (int t = 0; t < 2; t++)
#pragma unroll
                for (int u = 0; u < 8; u++)
                    mma16816(acc[t][u], a[t], b[u >> 1][(u & 1) << 1], b[u >> 1][((u & 1) << 1) + 1]);
        }
        __syncthreads();
    }

    // epilogue: d2 + minmax
    float lmx = -3.4e38f, lmn = 3.4e38f;
#pragma unroll
    for (int t = 0; t < 2; t++) {
        int r0 = bi + wm * 32 + t * 16 + (lane >> 2);
        float nx0 = g_nx[r0], nx1 = g_nx[r0 + 8];
#pragma unroll
        for (int u = 0; u < 8; u++) {
            int col = bj + wn * 64 + u * 8 + ((lane & 3) << 1);
            float nc0 = g_nc[col], nc1 = g_nc[col + 1];
            float d00 = (nx0 + nc0) - 2.0f * acc[t][u][0];
            float d01 = (nx0 + nc1) - 2.0f * acc[t][u][1];
            float d10 = (nx1 + nc0) - 2.0f * acc[t][u][2];
            float d11 = (nx1 + nc1) - 2.0f * acc[t][u][3];
            *(float2*)(g_Dm + (size_t)r0 * NK + col) = make_float2(d00, d01);
            *(float2*)(g_Dm + (size_t)(r0 + 8) * NK + col) = make_float2(d10, d11);
            lmx = fmaxf(lmx, fmaxf(fmaxf(d00, d01), fmaxf(d10, d11)));
            lmn = fminf(lmn, fminf(fminf(d00, d01), fminf(d10, d11)));
        }
    }
    for (int o = 16; o; o >>= 1) {
        lmx = fmaxf(lmx, __shfl_down_sync(0xffffffffu, lmx, o));
        lmn = fminf(lmn, __shfl_down_sync(0xffffffffu, lmn, o));
    }
    __shared__ float smx[8], smn[8];
    if (lane == 0) { smx[wid] = lmx; smn[wid] = lmn; }
    __syncthreads();
    if (tid == 0) {
#pragma unroll
        for (int w = 1; w < 8; w++) { lmx = fmaxf(lmx, smx[w]); lmn = fminf(lmn, smn[w]); }
        atomicMax(&g_maxbits, encf(lmx));
        atomicMin(&g_minbits, encf(lmn));
    }
}

__global__ void finalize_kernel() {
    float mx = decf(g_maxbits), mn = decf(g_minbits);
    float mid = (mx + mn) * 0.5f;
    g_midf = mid;
    g_rangef = (mx - mid) + 1e-8f;
}

// ---------------- fill: za/zaT + S partials ----------------
__global__ __launch_bounds__(256) void fill_kernel() {
    __shared__ float tile[64][65];
    __shared__ float sred[16];
    __shared__ float smb;
    const float midf = g_midf;
    const float rangef = g_rangef;
    const float cfh = -480.89834696298781f;
    const int tid = threadIdx.x;
    const int lane = tid & 31, warp = tid >> 5;
    const size_t i0 = (size_t)blockIdx.y * 64;
    const size_t j0 = (size_t)blockIdx.x * 64;
    const int r0 = tid >> 4;
    const int c4 = (tid & 15) << 2;

    float va[16];
    float mx = -3.4e38f;
#pragma unroll
    for (int k = 0; k < 4; k++) {
        int r = r0 + (k << 4);
        float4 d = *(const float4*)(g_Dm + (i0 + r) * NK + j0 + c4);
        float z0 = ((d.x - midf) / rangef) * cfh;
        float z1 = ((d.y - midf) / rangef) * cfh;
        float z2 = ((d.z - midf) / rangef) * cfh;
        float z3 = ((d.w - midf) / rangef) * cfh;
        va[k * 4 + 0] = z0; va[k * 4 + 1] = z1; va[k * 4 + 2] = z2; va[k * 4 + 3] = z3;
        tile[r][c4 + 0] = z0; tile[r][c4 + 1] = z1; tile[r][c4 + 2] = z2; tile[r][c4 + 3] = z3;
        *(float4*)(g_za + (i0 + r) * NK + j0 + c4) = make_float4(z0, z1, z2, z3);
        mx = fmaxf(mx, fmaxf(fmaxf(z0, z1), fmaxf(z2, z3)));
    }
    for (int o = 16; o; o >>= 1) mx = fmaxf(mx, __shfl_down_sync(0xffffffffu, mx, o));
    if (lane == 0) sred[warp] = mx;
    __syncthreads();
    if (tid == 0) {
        float m = sred[0];
#pragma unroll
        for (int w = 1; w < 8; w++) m = fmaxf(m, sred[w]);
        smb = floorf(m);
    }
    __syncthreads();
    const float mbf = smb;
    float s = 0.f;
#pragma unroll
    for (int k = 0; k < 16; k++) s += exp2f(va[k] - mbf);
    for (int o = 16; o; o >>= 1) s += __shfl_down_sync(0xffffffffu, s, o);
    if (lane == 0) sred[8 + warp] = s;
    __syncthreads();
    if (tid == 0) {
        float tot = 0.f;
#pragma unroll
        for (int w = 0; w < 8; w++) tot += sred[8 + w];
        g_Spart[blockIdx.y * 128 + blockIdx.x] = ldexp((double)tot, (int)mbf);
    }
#pragma unroll
    for (int k = 0; k < 4; k++) {
        int r = r0 + (k << 4);
        float4 v = make_float4(tile[c4 + 0][r], tile[c4 + 1][r], tile[c4 + 2][r], tile[c4 + 3][r]);
        *(float4*)(g_zaT + (j0 + r) * NK + i0 + c4) = v;
    }
}

__global__ __launch_bounds__(1024) void reduceS_kernel() {
    int tid = threadIdx.x;
    double s = 0.0;
#pragma unroll
    for (int k = 0; k < 16; k++) s += g_Spart[tid + k * 1024];
    __shared__ double sm[1024];
    sm[tid] = s;
    __syncthreads();
    for (int o = 512; o; o >>= 1) {
        if (tid < o) sm[tid] += sm[tid + o];
        __syncthreads();
    }
    if (tid == 0) g_S = sm[0];
}

__global__ void init_rc_kernel() {
    int t = blockIdx.x * blockDim.x + threadIdx.x;
    double S = g_S;
    if (t < NB) { g_r[t] = 1.0 / S; g_zr[t] = -log2_of_double(S); }
    if (t < NK) { g_c[t] = 1.0;     g_zc[t] = 0.0f; }
}

// ---------------- Sinkhorn pass ----------------
__global__ __launch_bounds__(256) void pass_kernel(int dir) {
    const float* __restrict__ ZA   = dir ? g_zaT : g_za;
    const float* __restrict__ zo   = dir ? g_zr  : g_zc;
    double* __restrict__      vec  = dir ? g_c   : g_r;
    float* __restrict__       zvec = dir ? g_zc  : g_zr;

    __shared__ float szo[NK];
    __shared__ float sred[16];
    __shared__ float sbc;
    const int tid = threadIdx.x;
    const int lane = tid & 31, warp = tid >> 5;
    for (int k = tid; k < NK / 4; k += 256)
        ((float4*)szo)[k] = ((const float4*)zo)[k];
    __syncthreads();
#pragma unroll 1
    for (int rr = 0; rr < 4; rr++) {
        const int i = (blockIdx.x << 2) + rr;
        const float4* a4 = (const float4*)(ZA + (size_t)i * NK);
        const float4* c4s = (const float4*)szo;
        float t[32];
        float mx = -3.4e38f;
#pragma unroll
        for (int k = 0; k < 8; k++) {
            int j4 = tid + (k << 8);
            float4 a = a4[j4];
            float4 c = c4s[j4];
            float t0 = a.x + c.x, t1 = a.y + c.y, t2 = a.z + c.z, t3 = a.w + c.w;
            t[k * 4 + 0] = t0; t[k * 4 + 1] = t1; t[k * 4 + 2] = t2; t[k * 4 + 3] = t3;
            mx = fmaxf(mx, fmaxf(fmaxf(t0, t1), fmaxf(t2, t3)));
        }
        for (int o = 16; o; o >>= 1) mx = fmaxf(mx, __shfl_down_sync(0xffffffffu, mx, o));
        if (lane == 0) sred[warp] = mx;
        __syncthreads();
        if (tid == 0) {
            float m = sred[0];
#pragma unroll
            for (int w = 1; w < 8; w++) m = fmaxf(m, sred[w]);
            sbc = floorf(m);
        }
        __syncthreads();
        const float mf = sbc;
        float s0 = 0.f, s1 = 0.f, s2 = 0.f, s3 = 0.f;
#pragma unroll
        for (int k = 0; k < 8; k++) {
            s0 += exp2f(t[k * 4 + 0] - mf);
            s1 += exp2f(t[k * 4 + 1] - mf);
            s2 += exp2f(t[k * 4 + 2] - mf);
            s3 += exp2f(t[k * 4 + 3] - mf);
        }
        float ss = (s0 + s1) + (s2 + s3);
        for (int o = 16; o; o >>= 1) ss += __shfl_down_sync(0xffffffffu, ss, o);
        if (lane == 0) sred[8 + warp] = ss;
        __syncthreads();
        if (tid == 0) {
            float tot = 0.f;
#pragma unroll
            for (int w = 0; w < 8; w++) tot += sred[8 + w];
            double y = ldexp((double)tot, (int)mf);
            double v = vec[i];
            double vn = v / ((v * y) + 1e-8) / 8192.0;
            vec[i] = vn;
            zvec[i] = log2_of_double(vn);
        }
        __syncthreads();
    }
}

// ---------------- probs + argmax ----------------
__global__ __launch_bounds__(256) void probs_kernel(float* __restrict__ out_probs,
                                                    float* __restrict__ out_idx) {
    __shared__ float szc[NK];
    __shared__ float sred[8];
    __shared__ int sidx[8];
    const int tid = threadIdx.x;
    const int lane = tid & 31, warp = tid >> 5;
    for (int k = tid; k < NK / 4; k += 256)
        ((float4*)szc)[k] = ((const float4*)g_zc)[k];
    __syncthreads();
#pragma unroll 1
    for (int rr = 0; rr < 4; rr++) {
        const int i = (blockIdx.x << 2) + rr;
        const float lR = log2_of_double(8192.0 * g_r[i]);
        const float4* a4 = (const float4*)(g_za + (size_t)i * NK);
        float4* o4 = (float4*)(out_probs + (size_t)i * NK);
        float best = -3.4e38f; int bj = 0x7FFFFFFF;
#pragma unroll
        for (int k = 0; k < 8; k++) {
            int j4 = tid + (k << 8);
            float4 a = a4[j4];
            float4 c = ((const float4*)szc)[j4];
            float t0 = a.x + c.x, t1 = a.y + c.y, t2 = a.z + c.z, t3 = a.w + c.w;
            o4[j4] = make_float4(exp2f(t0 + lR), exp2f(t1 + lR), exp2f(t2 + lR), exp2f(t3 + lR));
            int jb = j4 << 2;
            if (t0 > best) { best = t0; bj = jb; }
            if (t1 > best) { best = t1; bj = jb + 1; }
            if (t2 > best) { best = t2; bj = jb + 2; }
            if (t3 > best) { best = t3; bj = jb + 3; }
        }
        for (int o = 16; o; o >>= 1) {
            float ov = __shfl_down_sync(0xffffffffu, best, o);
            int oi = __shfl_down_sync(0xffffffffu, bj, o);
            if (ov > best || (ov == best && oi < bj)) { best = ov; bj = oi; }
        }
        if (lane == 0) { sred[warp] = best; sidx[warp] = bj; }
        __syncthreads();
        if (tid == 0) {
#pragma unroll
            for (int w = 1; w < 8; w++)
                if (sred[w] > best || (sred[w] == best && sidx[w] < bj)) { best = sred[w]; bj = sidx[w]; }
            g_idx[i] = bj;
            out_idx[i] = (float)bj;
        }
        __syncthreads();
    }
}

// ---------------- epilogue ----------------
__global__ __launch_bounds__(128) void epilogue_kernel(const float* __restrict__ X,
                                                       const float* __restrict__ C,
                                                       float* __restrict__ qh,
                                                       float* __restrict__ qs,
                                                       float* __restrict__ loss) {
    int i = blockIdx.x;
    int idx = g_idx[i];
    const float4* cb = (const float4*)(C + (size_t)idx * ND);
    const float4* xr = (const float4*)(X + (size_t)i * ND);
    float4* oh = (float4*)(qh + (size_t)i * ND);
    float4* os = (float4*)(qs + (size_t)i * ND);
    int t = threadIdx.x;
    float4 c4 = cb[t];
    float4 x4 = xr[t];
    oh[t] = c4;
    float dx = c4.x - x4.x, dy = c4.y - x4.y, dz = c4.z - x4.z, dw = c4.w - x4.w;
    os[t] = make_float4(dx + x4.x, dy + x4.y, dz + x4.z, dw + x4.w);
    double s = (double)dx * dx + (double)dy * dy + (double)dz * dz + (double)dw * dw;
    for (int o = 16; o; o >>= 1) s += __shfl_down_sync(0xffffffffu, s, o);
    __shared__ double sm[4];
    if ((t & 31) == 0) sm[t >> 5] = s;
    __syncthreads();
    if (t == 0) {
        double tot = (sm[0] + sm[1]) + (sm[2] + sm[3]);
        float cl = (float)(tot / (double)ND);
        loss[i] = cl + 0.25f * cl;
    }
}

// ---------------- launch ----------------
extern "C" void kernel_launch(void* const* d_in, const int* in_sizes, int n_in,
                              void* d_out, int out_size) {
    const float* X = (const float*)d_in[0];
    const float* C = (const float*)d_in[1];
    float* out = (float*)d_out;
    float* o_qh    = out;
    float* o_qs    = out + (size_t)NB * ND;
    float* o_idx   = out + 2ULL * NB * ND;
    float* o_probs = o_idx + NB;
    float* o_loss  = o_probs + NM;

    reset_kernel<<<1, 32>>>();
    norms_kernel<<<dim3(NB, 2), 128>>>(X, C);
    split_kernel<<<16384, 256>>>(X, C);
    mma_gemm_kernel<<<dim3(64, 64), 256>>>();
    finalize_kernel<<<1, 1>>>();
    fill_kernel<<<dim3(128, 128), 256>>>();
    reduceS_kernel<<<1, 1024>>>();
    init_rc_kernel<<<32, 256>>>();
    for (int it = 0; it < 50; it++) {
        pass_kernel<<<2048, 256>>>(0);
        pass_kernel<<<2048, 256>>>(1);
    }
    probs_kernel<<<2048, 256>>>(o_probs, o_idx);
    epilogue_kernel<<<NB, 128>>>(X, C, o_qh, o_qs, o_loss);
}